// round 12
// baseline (speedup 1.0000x reference)
#include <cuda_runtime.h>
#include <cuda_bf16.h>

// ---------------------------------------------------------------------------
// LaplacianRegularization
//   degree = segment_sum(w, row);  ys = bf16( y * rsqrt(degree)[:,None] )
//   out = mean_e( ||ys[row] - ys[col]||_2 * w_e )
//
// Inputs (metadata order):
//   d_in[0] : edge_index  int64 OR int32 (2, E)   (dtype detected on-device)
//   d_in[1] : edge_weights float32 (E,)
//   d_in[2] : y            float32 (N, 16)
// Output: 1 float
//
// k_main: L=2 gather (one LDG.U16 per edge: lanes 0-15 read row r = 1 line,
// lanes 16-31 read row c = 1 line) + logarithmic register-butterfly reduce
// (15 shfls per 16-edge batch instead of 4 shfls per edge; no redux.f32,
// which sm_103 lacks).
// ---------------------------------------------------------------------------

#define MAX_NODES 131072   // power of two >= N; index mask guarantees no trap

__device__ float    g_deg[MAX_NODES];                 // zero-init; re-zeroed by k_scale
__device__ __align__(128) __nv_bfloat16 g_ysb[MAX_NODES * 16];  // 32B bf16 rows
__device__ double   g_sum;                            // reset by k_main finalize
__device__ unsigned g_flag;                           // !=0 => int32 indices
__device__ unsigned g_count;                          // reset by k_main finalize

__device__ __forceinline__ int load_idx(const void* ei, long long pos, bool is32) {
    if (is32) return ((const int*)ei)[pos];
    return (int)((const long long*)ei)[pos];
}

// --- K0: dtype probe (1 warp) -------------------------------------------------
// int64 indices < 2^31 have zero hi-words; for int32 the odd words are node
// ids, nonzero w.h.p. over 512 samples of U[0, N).
__global__ void k_probe(const unsigned* __restrict__ words, int E) {
    int samples = E < 512 ? E : 512;
    unsigned v = 0;
    for (int i = threadIdx.x; i < samples; i += 32)
        v |= words[2 * i + 1];
    #pragma unroll
    for (int o = 16; o > 0; o >>= 1)
        v |= __shfl_xor_sync(0xFFFFFFFFu, v, o);
    if (threadIdx.x == 0) g_flag = v;
}

// --- K1: degree = segment_sum(w, row) ------------------------------------------
__global__ void k_degree(const void* __restrict__ ei,
                         const float* __restrict__ w, int E, int N) {
    int e = blockIdx.x * blockDim.x + threadIdx.x;
    if (e >= E) return;
    const bool is32 = (g_flag != 0u);
    int r = load_idx(ei, e, is32);
    if ((unsigned)r < (unsigned)N)
        atomicAdd(&g_deg[r], w[e]);
}

// --- K2: ys(bf16) = y * rsqrt(degree); also re-zero g_deg ------------------------
__global__ void k_scale(const float4* __restrict__ y4, int N) {
    int n = blockIdx.x * blockDim.x + threadIdx.x;
    if (n >= N) return;
    float s = rsqrtf(g_deg[n]);
    g_deg[n] = 0.0f;                      // restore invariant for next replay
    float4 u0 = __ldg(y4 + 4 * n + 0);
    float4 u1 = __ldg(y4 + 4 * n + 1);
    float4 u2 = __ldg(y4 + 4 * n + 2);
    float4 u3 = __ldg(y4 + 4 * n + 3);
    __nv_bfloat162 p0 = __float22bfloat162_rn(make_float2(u0.x * s, u0.y * s));
    __nv_bfloat162 p1 = __float22bfloat162_rn(make_float2(u0.z * s, u0.w * s));
    __nv_bfloat162 p2 = __float22bfloat162_rn(make_float2(u1.x * s, u1.y * s));
    __nv_bfloat162 p3 = __float22bfloat162_rn(make_float2(u1.z * s, u1.w * s));
    __nv_bfloat162 p4 = __float22bfloat162_rn(make_float2(u2.x * s, u2.y * s));
    __nv_bfloat162 p5 = __float22bfloat162_rn(make_float2(u2.z * s, u2.w * s));
    __nv_bfloat162 p6 = __float22bfloat162_rn(make_float2(u3.x * s, u3.y * s));
    __nv_bfloat162 p7 = __float22bfloat162_rn(make_float2(u3.z * s, u3.w * s));
    uint4 o0, o1;
    o0.x = *(unsigned*)&p0; o0.y = *(unsigned*)&p1;
    o0.z = *(unsigned*)&p2; o0.w = *(unsigned*)&p3;
    o1.x = *(unsigned*)&p4; o1.y = *(unsigned*)&p5;
    o1.z = *(unsigned*)&p6; o1.w = *(unsigned*)&p7;
    ((uint4*)g_ysb)[2 * n + 0] = o0;
    ((uint4*)g_ysb)[2 * n + 1] = o1;
}

// --- K3: L=2 gather + butterfly reduce + finalize --------------------------------
#define EDGES_PER_WARP  16
#define WARPS_PER_BLOCK 8
#define EDGES_PER_BLOCK (EDGES_PER_WARP * WARPS_PER_BLOCK)

__global__ void __launch_bounds__(256)
k_main(const void* __restrict__ ei,
       const float* __restrict__ w,
       float* __restrict__ out, int E, int N, int nblocks) {
    const bool is32 = (g_flag != 0u);
    const int  lane = threadIdx.x & 31;
    const int  warp = threadIdx.x >> 5;
    const int  half = lane >> 4;        // 0 = row side, 1 = col side
    const int  sub  = lane & 15;        // component index within 16-bf16 row

    const long long base = (long long)blockIdx.x * EDGES_PER_BLOCK
                         + (long long)warp * EDGES_PER_WARP;
    const long long epos = base + sub;
    const bool inr = (epos < (long long)E);

    // Role load: r for lanes 0-15, c for lanes 16-31 (one coalesced LDG).
    int mynode = 0;
    if (inr) mynode = load_idx(ei, half ? ((long long)E + epos) : epos, is32);

    // Per-edge validity bits: bit u (row side), bit 16+u (col side).
    unsigned valid = __ballot_sync(0xFFFFFFFFu, inr && (unsigned)mynode < (unsigned)N);
    mynode &= (MAX_NODES - 1);          // trap-proof; rows >= N are zero-filled

    // Weight on owner lanes 0-15, zeroed for invalid edges.
    float myw = 0.0f;
    if (half == 0 && inr) {
        bool ok = ((valid >> sub) & 1u) && ((valid >> (16 + sub)) & 1u);
        myw = ok ? __ldg(w + epos) : 0.0f;
    }

    // Gather: 16 independent LDG.U16, each touching exactly 2 cache lines.
    unsigned short vals[EDGES_PER_WARP];
    #pragma unroll
    for (int u = 0; u < EDGES_PER_WARP; u++) {
        int node = __shfl_sync(0xFFFFFFFFu, mynode, u + (lane & 16));
        vals[u] = ((const unsigned short*)g_ysb)[(unsigned)node * 16u + sub];
    }

    // d^2 per edge (identical in both halves after the xor-16 diff).
    float s16[16];
    #pragma unroll
    for (int u = 0; u < EDGES_PER_WARP; u++) {
        unsigned mine  = vals[u];
        unsigned other = __shfl_xor_sync(0xFFFFFFFFu, (unsigned)vals[u], 16);
        float a = __int_as_float(mine  << 16);   // bf16 -> f32 by shift
        float b = __int_as_float(other << 16);
        float d = a - b;
        s16[u] = d * d;
    }

    // Butterfly transpose-reduce: 4 rounds, 15 shfls total.
    // After round i, live register k holds the partial sum (over lanes agreeing
    // on bits 0..i of the component index) for edge u = k*2^(i+1) + (lane & (2^(i+1)-1)).
    float s8[8];
    {
        int bit = lane & 1;
        #pragma unroll
        for (int k = 0; k < 8; k++) {
            float keep = bit ? s16[2 * k + 1] : s16[2 * k];
            float send = bit ? s16[2 * k]     : s16[2 * k + 1];
            s8[k] = keep + __shfl_xor_sync(0xFFFFFFFFu, send, 1);
        }
    }
    float s4[4];
    {
        int bit = (lane >> 1) & 1;
        #pragma unroll
        for (int k = 0; k < 4; k++) {
            float keep = bit ? s8[2 * k + 1] : s8[2 * k];
            float send = bit ? s8[2 * k]     : s8[2 * k + 1];
            s4[k] = keep + __shfl_xor_sync(0xFFFFFFFFu, send, 2);
        }
    }
    float s2[2];
    {
        int bit = (lane >> 2) & 1;
        #pragma unroll
        for (int k = 0; k < 2; k++) {
            float keep = bit ? s4[2 * k + 1] : s4[2 * k];
            float send = bit ? s4[2 * k]     : s4[2 * k + 1];
            s2[k] = keep + __shfl_xor_sync(0xFFFFFFFFu, send, 4);
        }
    }
    float norm2;
    {
        int bit = (lane >> 3) & 1;
        float keep = bit ? s2[1] : s2[0];
        float send = bit ? s2[0] : s2[1];
        norm2 = keep + __shfl_xor_sync(0xFFFFFFFFu, send, 8);
    }
    // Lane l now holds norm^2 of edge (l & 15); upper half has myw = 0.
    float val = sqrtf(norm2) * myw;

    // warp + block reduce
    #pragma unroll
    for (int o = 16; o > 0; o >>= 1)
        val += __shfl_down_sync(0xFFFFFFFFu, val, o);

    __shared__ float s_warp[WARPS_PER_BLOCK];
    if (lane == 0) s_warp[warp] = val;
    __syncthreads();

    if (warp == 0) {
        val = (lane < WARPS_PER_BLOCK) ? s_warp[lane] : 0.0f;
        #pragma unroll
        for (int o = 4; o > 0; o >>= 1)
            val += __shfl_down_sync(0xFFFFFFFFu, val, o);
        if (lane == 0) {
            atomicAdd(&g_sum, (double)val);
            __threadfence();
            unsigned ticket = atomicInc(&g_count, 0xFFFFFFFFu);
            if (ticket == (unsigned)(nblocks - 1)) {
                *out = (float)(g_sum / (double)E);
                g_sum = 0.0;          // restore invariants for next replay
                g_count = 0u;
            }
        }
    }
}

extern "C" void kernel_launch(void* const* d_in, const int* in_sizes, int n_in,
                              void* d_out, int out_size) {
    const void*   ei  = d_in[0];
    const float*  w   = (const float*)d_in[1];
    const float4* y4  = (const float4*)d_in[2];
    float*        out = (float*)d_out;

    const int E = in_sizes[1];       // number of edges
    const int N = in_sizes[2] / 16;  // number of nodes

    const int T = 256;
    int blocksE = (E + T - 1) / T;
    int blocksS = (N + T - 1) / T;
    int blocksM = (E + EDGES_PER_BLOCK - 1) / EDGES_PER_BLOCK;

    k_probe <<<1, 32>>>((const unsigned*)ei, E);
    k_degree<<<blocksE, T>>>(ei, w, E, N);
    k_scale <<<blocksS, T>>>(y4, N);
    k_main  <<<blocksM, T>>>(ei, w, out, E, N, blocksM);
}

// round 15
// speedup vs baseline: 1.3531x; 1.3531x over previous
#include <cuda_runtime.h>

// ---------------------------------------------------------------------------
// LaplacianRegularization
//   degree = segment_sum(w, row);  ys = y * rsqrt(degree)[:,None]
//   out = mean_e( ||ys[row] - ys[col]||_2 * w_e )
//
// Inputs (metadata order):
//   d_in[0] : edge_index  int64 OR int32 (2, E)   (dtype detected on-device)
//   d_in[1] : edge_weights float32 (E,)
//   d_in[2] : y            float32 (N, 16)
// Output: 1 float
//
// 4 launches: k_probe (1 warp dtype detect), k_degree (atomics),
// k_scale (ys = y*rsqrt(deg), re-zeroes g_deg), k_main (persistent quad
// gather: 4 lanes per row, 4 edges per quad per tile, grid-stride tiles
// to smooth cross-CTA L1tex-queue spread; block reduce once per block).
// ---------------------------------------------------------------------------

#define MAX_NODES 131072

__device__ float    g_deg[MAX_NODES];        // zero-init; re-zeroed by k_scale
__device__ float4   g_ys[MAX_NODES * 4];     // scaled fp32 rows (64B each)
__device__ double   g_sum;                   // reset by k_main finalize
__device__ unsigned g_flag;                  // !=0 => int32 indices
__device__ unsigned g_count;                 // reset by k_main finalize

__device__ __forceinline__ int load_idx(const void* ei, long long pos, bool is32) {
    if (is32) return ((const int*)ei)[pos];
    return (int)((const long long*)ei)[pos];
}

// --- K0: dtype probe (1 warp) ------------------------------------------------
// int64 indices < 2^31 have zero hi-words; for int32 the odd words are node
// ids, nonzero w.h.p. over 512 samples of U[0, N).
__global__ void k_probe(const unsigned* __restrict__ words, int E) {
    int samples = E < 512 ? E : 512;
    unsigned v = 0;
    for (int i = threadIdx.x; i < samples; i += 32)
        v |= words[2 * i + 1];
    #pragma unroll
    for (int o = 16; o > 0; o >>= 1)
        v |= __shfl_xor_sync(0xFFFFFFFFu, v, o);
    if (threadIdx.x == 0) g_flag = v;
}

// --- K1: degree = segment_sum(w, row) -----------------------------------------
__global__ void k_degree(const void* __restrict__ ei,
                         const float* __restrict__ w, int E, int N) {
    int e = blockIdx.x * blockDim.x + threadIdx.x;
    if (e >= E) return;
    const bool is32 = (g_flag != 0u);
    int r = load_idx(ei, e, is32);
    if ((unsigned)r < (unsigned)N)
        atomicAdd(&g_deg[r], w[e]);
}

// --- K2: ys = y * rsqrt(degree); re-zero g_deg ----------------------------------
// One thread per float4 (4 threads per node row). All 4 lanes of a node sit in
// the same warp, so the broadcast deg load issues before the lane-0 zero store.
__global__ void k_scale(const float4* __restrict__ y4, int N) {
    int i = blockIdx.x * blockDim.x + threadIdx.x;   // float4 index
    if (i >= N * 4) return;
    int node = i >> 2;
    float s = rsqrtf(g_deg[node]);
    if ((i & 3) == 0) g_deg[node] = 0.0f;            // restore invariant
    float4 v = __ldg(y4 + i);
    v.x *= s; v.y *= s; v.z *= s; v.w *= s;
    g_ys[i] = v;
}

// --- K3: persistent quad-gather per-edge norm + reduce + finalize ---------------
// Tile = 256 edges. Quad layout: 4 lanes per edge row (one float4 each),
// 4 edges per quad per tile. Blocks grid-stride over tiles (~14 tiles each),
// accumulating in registers; one block reduce + one double atomic per block.
#define EDGES_PER_TILE 256

__global__ void __launch_bounds__(256)
k_main(const void* __restrict__ ei,
       const float* __restrict__ w,
       float* __restrict__ out, int E, int N, int ntiles) {
    const bool is32  = (g_flag != 0u);
    const int  lane4 = threadIdx.x & 3;
    const int  qid   = threadIdx.x >> 2;

    float val = 0.0f;

    for (int tile = blockIdx.x; tile < ntiles; tile += gridDim.x) {
        const long long base = (long long)tile * EDGES_PER_TILE + (long long)qid * 4;

        int   r[4], c[4];
        float we[4];
        bool  full = (base + 3 < (long long)E);

        if (full) {
            if (is32) {
                const int4 rv = __ldg((const int4*)((const int*)ei + base));
                const int4 cv = __ldg((const int4*)((const int*)ei + (long long)E + base));
                r[0] = rv.x; r[1] = rv.y; r[2] = rv.z; r[3] = rv.w;
                c[0] = cv.x; c[1] = cv.y; c[2] = cv.z; c[3] = cv.w;
            } else {
                const longlong2 r01 = __ldg((const longlong2*)((const long long*)ei + base));
                const longlong2 r23 = __ldg((const longlong2*)((const long long*)ei + base + 2));
                const longlong2 c01 = __ldg((const longlong2*)((const long long*)ei + (long long)E + base));
                const longlong2 c23 = __ldg((const longlong2*)((const long long*)ei + (long long)E + base + 2));
                r[0] = (int)r01.x; r[1] = (int)r01.y; r[2] = (int)r23.x; r[3] = (int)r23.y;
                c[0] = (int)c01.x; c[1] = (int)c01.y; c[2] = (int)c23.x; c[3] = (int)c23.y;
            }
            const float4 wv = __ldg((const float4*)(w + base));
            we[0] = wv.x; we[1] = wv.y; we[2] = wv.z; we[3] = wv.w;
        } else {
            #pragma unroll
            for (int k = 0; k < 4; k++) {
                long long e = base + k;
                if (e < (long long)E) {
                    r[k]  = load_idx(ei, e, is32);
                    c[k]  = load_idx(ei, (long long)E + e, is32);
                    we[k] = w[e];
                } else { r[k] = -1; c[k] = -1; we[k] = 0.0f; }
            }
        }

        // 8 independent random row-gathers per thread (front-batched MLP).
        float4 a[4], b[4];
        #pragma unroll
        for (int k = 0; k < 4; k++) {
            bool ok = ((unsigned)r[k] < (unsigned)N) && ((unsigned)c[k] < (unsigned)N);
            if (ok) {
                a[k] = g_ys[(size_t)r[k] * 4 + lane4];
                b[k] = g_ys[(size_t)c[k] * 4 + lane4];
            } else {
                a[k] = make_float4(0, 0, 0, 0);
                b[k] = make_float4(0, 0, 0, 0);
                we[k] = 0.0f;
            }
        }

        #pragma unroll
        for (int k = 0; k < 4; k++) {
            float d0 = a[k].x - b[k].x;
            float d1 = a[k].y - b[k].y;
            float d2 = a[k].z - b[k].z;
            float d3 = a[k].w - b[k].w;
            float acc = d0 * d0;
            acc = fmaf(d1, d1, acc);
            acc = fmaf(d2, d2, acc);
            acc = fmaf(d3, d3, acc);
            // quad reduce (lanes differ only in lane4 bits)
            acc += __shfl_xor_sync(0xFFFFFFFFu, acc, 1);
            acc += __shfl_xor_sync(0xFFFFFFFFu, acc, 2);
            if (lane4 == 0) val += sqrtf(acc) * we[k];
        }
    }

    // warp + block reduce (once per block)
    #pragma unroll
    for (int o = 16; o > 0; o >>= 1)
        val += __shfl_down_sync(0xFFFFFFFFu, val, o);

    __shared__ float s_warp[8];
    int lane = threadIdx.x & 31;
    int warp = threadIdx.x >> 5;
    if (lane == 0) s_warp[warp] = val;
    __syncthreads();

    if (warp == 0) {
        val = (lane < (int)(blockDim.x >> 5)) ? s_warp[lane] : 0.0f;
        #pragma unroll
        for (int o = 4; o > 0; o >>= 1)
            val += __shfl_down_sync(0xFFFFFFFFu, val, o);
        if (lane == 0) {
            atomicAdd(&g_sum, (double)val);
            __threadfence();
            unsigned ticket = atomicInc(&g_count, 0xFFFFFFFFu);
            if (ticket == (unsigned)(gridDim.x - 1)) {
                *out = (float)(g_sum / (double)E);
                g_sum = 0.0;          // restore invariants for next replay
                g_count = 0u;
            }
        }
    }
}

extern "C" void kernel_launch(void* const* d_in, const int* in_sizes, int n_in,
                              void* d_out, int out_size) {
    const void*   ei  = d_in[0];
    const float*  w   = (const float*)d_in[1];
    const float4* y4  = (const float4*)d_in[2];
    float*        out = (float*)d_out;

    const int E = in_sizes[1];       // number of edges
    const int N = in_sizes[2] / 16;  // number of nodes

    const int T = 256;
    int blocksE = (E + T - 1) / T;
    int blocksS = (N * 4 + T - 1) / T;
    int ntiles  = (E + EDGES_PER_TILE - 1) / EDGES_PER_TILE;
    int blocksM = 6 * 148;                   // ~6 CTAs/SM persistent
    if (blocksM > ntiles) blocksM = ntiles;

    k_probe <<<1, 32>>>((const unsigned*)ei, E);
    k_degree<<<blocksE, T>>>(ei, w, E, N);
    k_scale <<<blocksS, T>>>(y4, N);
    k_main  <<<blocksM, T>>>(ei, w, out, E, N, ntiles);
}